// round 1
// baseline (speedup 1.0000x reference)
#include <cuda_runtime.h>

// DEMA decomposition: x (32, 2048, 512) f32 -> (res, ma) each same shape.
//   s0 = x[:,0,:]; b0 = x[:,1,:] - s0
//   s_t = a*x_t + (1-a)*(s_{t-1} + b_{t-1})
//   b_t = be*(s_t - s_{t-1}) + (1-be)*b_{t-1}
//   ma = [s0, s1, ..., s_{T-1}], res = x - ma
//
// Parallelization: recurrence matrix has spectral radius sqrt(0.7)~0.837, so
// state influence decays ~0.837^W. Split T into chunks of L=128; each chunk
// (except chunk 0) reconstructs its entry state from a W=96 warmup window
// (error ~4e-8 << 1e-3 tolerance). Warmup reads overlap the previous chunk's
// main reads -> L2 hits; DRAM traffic stays ~384 MiB (pure streaming bound).

#define ALPHA 0.3f
#define BETA  0.3f

#define BDIM 32
#define TDIM 2048
#define FDIM 512

#define CHUNK 128     // timesteps per chunk
#define WARM  96      // warmup window for chunks >= 1
#define NCHUNK (TDIM / CHUNK)   // 16
#define F4    (FDIM / 4)        // 128 float4 per row

__device__ __forceinline__ void dema_step(float4& s, float4& bb, const float4 xt) {
    // s_new = 0.3*x + 0.7*(s+b);  b_new = 0.3*(s_new - s) + 0.7*b
    float4 sn;
    sn.x = fmaf(1.0f - ALPHA, s.x + bb.x, ALPHA * xt.x);
    sn.y = fmaf(1.0f - ALPHA, s.y + bb.y, ALPHA * xt.y);
    sn.z = fmaf(1.0f - ALPHA, s.z + bb.z, ALPHA * xt.z);
    sn.w = fmaf(1.0f - ALPHA, s.w + bb.w, ALPHA * xt.w);
    bb.x = fmaf(BETA, sn.x - s.x, (1.0f - BETA) * bb.x);
    bb.y = fmaf(BETA, sn.y - s.y, (1.0f - BETA) * bb.y);
    bb.z = fmaf(BETA, sn.z - s.z, (1.0f - BETA) * bb.z);
    bb.w = fmaf(BETA, sn.w - s.w, (1.0f - BETA) * bb.w);
    s = sn;
}

__global__ void __launch_bounds__(F4, 8) dema_kernel(
    const float* __restrict__ x, float* __restrict__ out)
{
    const int c  = blockIdx.x;      // chunk index 0..15
    const int b  = blockIdx.y;      // batch 0..31
    const int f4 = threadIdx.x;     // 0..127, each owns 4 contiguous features

    const float4* __restrict__ xb =
        reinterpret_cast<const float4*>(x + (size_t)b * TDIM * FDIM) + f4;
    float4* __restrict__ res =
        reinterpret_cast<float4*>(out) + (size_t)b * TDIM * F4 + f4;
    float4* __restrict__ ma =
        reinterpret_cast<float4*>(out + (size_t)BDIM * TDIM * FDIM)
        + (size_t)b * TDIM * F4 + f4;

    const int t0 = c * CHUNK;
    float4 s, bb;
    int t;

    if (c == 0) {
        // Exact init
        float4 x0 = xb[0];
        float4 x1 = xb[F4];
        s = x0;
        bb.x = x1.x - x0.x; bb.y = x1.y - x0.y;
        bb.z = x1.z - x0.z; bb.w = x1.w - x0.w;
        ma[0] = s;
        res[0] = make_float4(0.0f, 0.0f, 0.0f, 0.0f);
        t = 1;
    } else {
        // Approximate init + warmup: state error decays as 0.837^WARM ~ 4e-8
        const int tw = t0 - WARM;
        float4 x0 = xb[tw * F4];
        float4 x1 = xb[(tw + 1) * F4];
        s = x0;
        bb.x = x1.x - x0.x; bb.y = x1.y - x0.y;
        bb.z = x1.z - x0.z; bb.w = x1.w - x0.w;
        #pragma unroll 4
        for (int tt = tw + 1; tt < t0; ++tt) {
            float4 xt = xb[tt * F4];
            dema_step(s, bb, xt);
        }
        t = t0;
    }

    const int tend = t0 + CHUNK;
    #pragma unroll 4
    for (; t < tend; ++t) {
        float4 xt = xb[t * F4];
        dema_step(s, bb, xt);
        ma[t * F4] = s;
        float4 r;
        r.x = xt.x - s.x; r.y = xt.y - s.y;
        r.z = xt.z - s.z; r.w = xt.w - s.w;
        res[t * F4] = r;
    }
}

extern "C" void kernel_launch(void* const* d_in, const int* in_sizes, int n_in,
                              void* d_out, int out_size)
{
    const float* x = (const float*)d_in[0];
    float* out = (float*)d_out;
    dim3 grid(NCHUNK, BDIM);
    dema_kernel<<<grid, F4>>>(x, out);
}

// round 2
// speedup vs baseline: 1.0036x; 1.0036x over previous
#include <cuda_runtime.h>

// DEMA decomposition: x (32, 2048, 512) f32 -> (res, ma) each same shape.
//   s0 = x[:,0,:]; b0 = x[:,1,:] - s0
//   s_t = a*x_t + (1-a)*(s_{t-1} + b_{t-1})
//   b_t = be*(s_t - s_{t-1}) + (1-be)*b_{t-1}
//   ma = [s0..s_{T-1}], res = x - ma
//
// Chunked-scan parallelization: recurrence matrix spectral radius sqrt(0.7)
// ~0.837 -> state influence decays 0.837^W. R1 measured rel_err 1.06e-7 at
// W=96, matching the model. W=64 -> ~1.1e-5, still 100x under tolerance.
// CHUNK=64 doubles thread count vs R1 (occ 19.5% -> ~43%) to raise MLP and
// push DRAM% from 69 toward saturation. Warmup reads hit L2 (neighbor chunk's
// concurrently-hot lines); streaming stores (__stcs) keep outputs from
// evicting x out of L2.

#define ALPHA 0.3f
#define BETA  0.3f

#define BDIM 32
#define TDIM 2048
#define FDIM 512

#define CHUNK 64      // timesteps per chunk
#define WARM  64      // warmup window for chunks >= 1
#define NCHUNK (TDIM / CHUNK)   // 32
#define F4    (FDIM / 4)        // 128 float4 per row

__device__ __forceinline__ void dema_step(float4& s, float4& bb, const float4 xt) {
    float4 sn;
    sn.x = fmaf(1.0f - ALPHA, s.x + bb.x, ALPHA * xt.x);
    sn.y = fmaf(1.0f - ALPHA, s.y + bb.y, ALPHA * xt.y);
    sn.z = fmaf(1.0f - ALPHA, s.z + bb.z, ALPHA * xt.z);
    sn.w = fmaf(1.0f - ALPHA, s.w + bb.w, ALPHA * xt.w);
    bb.x = fmaf(BETA, sn.x - s.x, (1.0f - BETA) * bb.x);
    bb.y = fmaf(BETA, sn.y - s.y, (1.0f - BETA) * bb.y);
    bb.z = fmaf(BETA, sn.z - s.z, (1.0f - BETA) * bb.z);
    bb.w = fmaf(BETA, sn.w - s.w, (1.0f - BETA) * bb.w);
    s = sn;
}

__global__ void __launch_bounds__(F4, 8) dema_kernel(
    const float* __restrict__ x, float* __restrict__ out)
{
    const int c  = blockIdx.x;      // chunk index 0..31
    const int b  = blockIdx.y;      // batch 0..31
    const int f4 = threadIdx.x;     // 0..127, each owns 4 contiguous features

    const float4* __restrict__ xb =
        reinterpret_cast<const float4*>(x + (size_t)b * TDIM * FDIM) + f4;
    float4* __restrict__ res =
        reinterpret_cast<float4*>(out) + (size_t)b * TDIM * F4 + f4;
    float4* __restrict__ ma =
        reinterpret_cast<float4*>(out + (size_t)BDIM * TDIM * FDIM)
        + (size_t)b * TDIM * F4 + f4;

    const int t0 = c * CHUNK;
    float4 s, bb;
    int t;

    if (c == 0) {
        // Exact init
        float4 x0 = xb[0];
        float4 x1 = xb[F4];
        s = x0;
        bb.x = x1.x - x0.x; bb.y = x1.y - x0.y;
        bb.z = x1.z - x0.z; bb.w = x1.w - x0.w;
        __stcs(&ma[0], s);
        __stcs(&res[0], make_float4(0.0f, 0.0f, 0.0f, 0.0f));
        t = 1;
    } else {
        // Approximate init + warmup: state error decays as 0.837^WARM ~ 1e-5
        const int tw = t0 - WARM;
        float4 x0 = xb[tw * F4];
        float4 x1 = xb[(tw + 1) * F4];
        s = x0;
        bb.x = x1.x - x0.x; bb.y = x1.y - x0.y;
        bb.z = x1.z - x0.z; bb.w = x1.w - x0.w;
        #pragma unroll 4
        for (int tt = tw + 1; tt < t0; ++tt) {
            float4 xt = xb[tt * F4];
            dema_step(s, bb, xt);
        }
        t = t0;
    }

    const int tend = t0 + CHUNK;
    #pragma unroll 4
    for (; t < tend; ++t) {
        float4 xt = xb[t * F4];
        dema_step(s, bb, xt);
        __stcs(&ma[t * F4], s);
        float4 r;
        r.x = xt.x - s.x; r.y = xt.y - s.y;
        r.z = xt.z - s.z; r.w = xt.w - s.w;
        __stcs(&res[t * F4], r);
    }
}

extern "C" void kernel_launch(void* const* d_in, const int* in_sizes, int n_in,
                              void* d_out, int out_size)
{
    const float* x = (const float*)d_in[0];
    float* out = (float*)d_out;
    dim3 grid(NCHUNK, BDIM);
    dema_kernel<<<grid, F4>>>(x, out);
}